// round 4
// baseline (speedup 1.0000x reference)
#include <cuda_runtime.h>
#include <cstdint>

// FeedForwardQuantum — sm_100 base-target edition (no tcgen05 on this toolchain).
//   q = cos(x[:, :NQ] + theta)                  (qcos_kernel -> g_q)
//   out = relu(q @ W1^T + b1) @ W2^T + b2       (fused; A computed on the fly)
// GEMM2: M=16384, N=E=1024, K=FFN=4096. tf32 mma.sync (m16n8k8), fp32 accumulate.
//
// Key layout: A/B tiles in SMEM stored "pair-permuted": k-columns (c, c+4) of each
// 8-wide k-group sit in adjacent floats, so every MMA fragment pair is ONE LDS.64.
// 16B-chunk XOR swizzle by (row&7) makes LDS.64/STS.64 minimal-2-phase conflict-free.

#define NQ      10
#define BM      64
#define BN      256
#define BK      32
#define THREADS 512

// ---- shared memory layout (bytes) ----
#define A_STAGE   (BM * 128)                 // 8192
#define B_STAGE   (BN * 128)                 // 32768
#define W1_STAGE  (352 * 4)                  // 10x32 transposed W1 + 32 b1 = 1408
#define SM_A      0
#define SM_B      (SM_A + 2 * A_STAGE)       // 16384
#define SM_Q      (SM_B + 2 * B_STAGE)       // 81920
#define SM_W1     (SM_Q + BM * 12 * 4)       // 84992
#define SM_TOTAL  (SM_W1 + 2 * W1_STAGE)     // 87808

__device__ float g_q[32768 * NQ];

__global__ void qcos_kernel(const float* __restrict__ x,
                            const float* __restrict__ theta,
                            int M, int E) {
    int t = blockIdx.x * blockDim.x + threadIdx.x;
    if (t >= M) return;
    const float* xr = x + (size_t)t * E;
#pragma unroll
    for (int i = 0; i < NQ; i++) g_q[t * NQ + i] = cosf(xr[i] + __ldg(theta + i));
}

__device__ __forceinline__ uint32_t f2tf32(float f) {
    uint32_t r;
    asm("cvt.rna.tf32.f32 %0, %1;" : "=r"(r) : "f"(f));
    return r;
}

#define MMA_TF32(d, a, b)                                               \
    asm volatile(                                                       \
        "mma.sync.aligned.m16n8k8.row.col.f32.tf32.tf32.f32 "           \
        "{%0,%1,%2,%3}, {%4,%5,%6,%7}, {%8,%9}, {%0,%1,%2,%3};"         \
        : "+f"((d)[0]), "+f"((d)[1]), "+f"((d)[2]), "+f"((d)[3])        \
        : "r"((a)[0]), "r"((a)[1]), "r"((a)[2]), "r"((a)[3]),           \
          "r"((b)[0]), "r"((b)[1]))

// Physical byte offset within one tile stage.
// word = kk*8 + slot, slot = 2c (pair (c, c+4) stored at slots 2c, 2c+1).
// Row stride 128B; XOR swizzle of the 16B-chunk bits by (row & 7).
__device__ __forceinline__ uint32_t frag_off(int row, int word) {
    return (uint32_t)row * 128u + ((uint32_t)(word * 4) ^ (((uint32_t)row & 7u) << 4));
}

__global__ void __launch_bounds__(THREADS, 1)
ffn_kernel(const float* __restrict__ W1,
           const float* __restrict__ b1,
           const float* __restrict__ W2,
           const float* __restrict__ b2,
           float* __restrict__ out,
           int M, int K, int E) {
    extern __shared__ char smem[];

    const int tid  = threadIdx.x;
    const int warp = tid >> 5;
    const int lane = tid & 31;
    const int g    = lane >> 2;          // groupID
    const int tg   = lane & 3;           // thread-in-group
    const int wm   = (warp & 1) * 32;    // warp M offset (2 x 8 warp grid)
    const int wn   = (warp >> 1) * 32;   // warp N offset
    const int mblk = blockIdx.x * BM;
    const int nblk = blockIdx.y * BN;
    const int NC   = K / BK;             // 128 chunks

    float* qs = (float*)(smem + SM_Q);

    // ---- prologue: q slab (rows padded to 12 floats) ----
    {
        const float* qg = g_q + (size_t)mblk * NQ;
        for (int i = tid; i < BM * NQ; i += THREADS)
            qs[(i / NQ) * 12 + (i % NQ)] = qg[i];
    }
    // ---- prologue: stage W1/b1 chunk 0 (transposed: w1t[i][k] at i*32+k) ----
    {
        float* w1s = (float*)(smem + SM_W1);
        if (tid < 320) {
            float v = W1[tid];           // chunk 0: rows 0..31 contiguous (32*10 floats)
            int k = tid / NQ;
            int i = tid - k * NQ;
            w1s[i * 32 + k] = v;
        } else if (tid < 352) {
            w1s[320 + (tid - 320)] = b1[tid - 320];
        }
    }

    // ---- B prefetch registers: thread covers W2 row n, 16 k (half of chunk) ----
    const int bn    = tid >> 1;
    const int bhalf = tid & 1;
    float4 breg[4];
    {
        const float* src = W2 + (size_t)(nblk + bn) * K + bhalf * 16;
#pragma unroll
        for (int j = 0; j < 4; j++) breg[j] = *(const float4*)(src + 4 * j);
    }

    // ---- A-compute assignment: 2 rows x 1 col-pair per thread ----
    const int pid = tid & 15;
    const int akk = pid >> 2;            // k-group 0..3
    const int ac  = pid & 3;             // pair base col 0..3
    const int am  = (tid >> 4) * 2;      // rows am, am+1

    float acc[2][4][4];
#pragma unroll
    for (int mi = 0; mi < 2; mi++)
#pragma unroll
        for (int ni = 0; ni < 4; ni++)
#pragma unroll
            for (int j = 0; j < 4; j++) acc[mi][ni][j] = 0.f;

    __syncthreads();

    for (int kci = 0; kci < NC; kci++) {
        const int kc = kci * BK;
        const int s  = kci & 1;
        char* As = smem + SM_A + s * A_STAGE;
        char* Bs = smem + SM_B + s * B_STAGE;

        // ======== phase A: fill stage s ========
        // ---- B: cvt + pair-pack + STS.64 ----
        {
            const float* bp = (const float*)breg;   // 16 floats, k-offsets bhalf*16 + 0..15
#pragma unroll
            for (int kk2 = 0; kk2 < 2; kk2++) {
                const int kk = bhalf * 2 + kk2;
#pragma unroll
                for (int c = 0; c < 4; c++) {
                    float2 pr;
                    pr.x = __uint_as_float(f2tf32(bp[kk2 * 8 + c]));
                    pr.y = __uint_as_float(f2tf32(bp[kk2 * 8 + c + 4]));
                    *(float2*)(Bs + frag_off(bn, kk * 8 + 2 * c)) = pr;
                }
            }
        }
        // ---- A: h = relu(q . W1 + b1), cvt, pair-pack, STS.64 ----
        {
            const float* w1s = (const float*)(smem + SM_W1 + s * W1_STAGE);
            const int kA = akk * 8 + ac;
            const int kB = kA + 4;
            float wA[NQ], wB[NQ];
#pragma unroll
            for (int i = 0; i < NQ; i++) { wA[i] = w1s[i * 32 + kA]; wB[i] = w1s[i * 32 + kB]; }
            const float bA = w1s[320 + kA];
            const float bB = w1s[320 + kB];
#pragma unroll
            for (int r = 0; r < 2; r++) {
                const int m = am + r;
                const float* qr = qs + m * 12;
                float sA = bA, sB = bB;
#pragma unroll
                for (int i = 0; i < NQ; i++) {
                    const float qv = qr[i];
                    sA = fmaf(qv, wA[i], sA);
                    sB = fmaf(qv, wB[i], sB);
                }
                float2 pr;
                pr.x = __uint_as_float(f2tf32(fmaxf(sA, 0.f)));
                pr.y = __uint_as_float(f2tf32(fmaxf(sB, 0.f)));
                *(float2*)(As + frag_off(m, akk * 8 + 2 * ac)) = pr;
            }
        }

        __syncthreads();

        // ======== phase B: prefetch next chunk, MMA over stage s ========
        if (kci + 1 < NC) {
            const int kcn = kc + BK;
            // W1/b1 staging (transposed) into stage s^1
            float* w1s = (float*)(smem + SM_W1 + (s ^ 1) * W1_STAGE);
            if (tid < 320) {
                float v = W1[kcn * NQ + tid];
                int k = tid / NQ;
                int i = tid - k * NQ;
                w1s[i * 32 + k] = v;
            } else if (tid < 352) {
                w1s[320 + (tid - 320)] = b1[kcn + (tid - 320)];
            }
            // B prefetch
            const float* src = W2 + (size_t)(nblk + bn) * K + kcn + bhalf * 16;
#pragma unroll
            for (int j = 0; j < 4; j++) breg[j] = *(const float4*)(src + 4 * j);
        }

        // ---- MMA: 4 k-steps; all fragment loads are LDS.64 ----
#pragma unroll
        for (int kk = 0; kk < 4; kk++) {
            const int w0 = kk * 8 + 2 * tg;
            uint32_t a[2][4];
#pragma unroll
            for (int mi = 0; mi < 2; mi++) {
                const int r = wm + mi * 16 + g;
                float2 pa = *(const float2*)(As + frag_off(r,     w0));
                float2 pb = *(const float2*)(As + frag_off(r + 8, w0));
                a[mi][0] = __float_as_uint(pa.x);   // A[r][tg]
                a[mi][1] = __float_as_uint(pb.x);   // A[r+8][tg]
                a[mi][2] = __float_as_uint(pa.y);   // A[r][tg+4]
                a[mi][3] = __float_as_uint(pb.y);   // A[r+8][tg+4]
            }
#pragma unroll
            for (int ni = 0; ni < 4; ni++) {
                const int n = wn + ni * 8 + g;
                float2 pbv = *(const float2*)(Bs + frag_off(n, w0));
                uint32_t b[2];
                b[0] = __float_as_uint(pbv.x);      // B[n][tg]
                b[1] = __float_as_uint(pbv.y);      // B[n][tg+4]
                MMA_TF32(acc[0][ni], a[0], b);
                MMA_TF32(acc[1][ni], a[1], b);
            }
        }

        __syncthreads();
    }

    // ---- epilogue: out = acc + b2 ----
#pragma unroll
    for (int ni = 0; ni < 4; ni++) {
        const int n0 = nblk + wn + ni * 8 + 2 * tg;
        const float2 bv = *(const float2*)(b2 + n0);
#pragma unroll
        for (int mi = 0; mi < 2; mi++) {
            const int m0 = mblk + wm + mi * 16 + g;
            float2 o0, o1;
            o0.x = acc[mi][ni][0] + bv.x;  o0.y = acc[mi][ni][1] + bv.y;
            o1.x = acc[mi][ni][2] + bv.x;  o1.y = acc[mi][ni][3] + bv.y;
            *(float2*)(out + (size_t)m0 * E + n0)       = o0;
            *(float2*)(out + (size_t)(m0 + 8) * E + n0) = o1;
        }
    }
}

extern "C" void kernel_launch(void* const* d_in, const int* in_sizes, int n_in,
                              void* d_out, int out_size) {
    const float* x     = (const float*)d_in[0];
    const float* theta = (const float*)d_in[1];
    const float* W1    = (const float*)d_in[2];
    const float* b1    = (const float*)d_in[3];
    const float* W2    = (const float*)d_in[4];
    const float* b2    = (const float*)d_in[5];
    float* out = (float*)d_out;

    const int E   = in_sizes[5];      // 1024
    const int FFN = in_sizes[3];      // 4096
    const int M   = in_sizes[0] / E;  // 16384

    qcos_kernel<<<(M + 255) / 256, 256>>>(x, theta, M, E);

    cudaFuncSetAttribute(ffn_kernel, cudaFuncAttributeMaxDynamicSharedMemorySize, SM_TOTAL);
    dim3 grid(M / BM, E / BN);        // (256, 4); x fastest -> W2 n-slice stays hot in L2
    ffn_kernel<<<grid, THREADS, SM_TOTAL>>>(W1, b1, W2, b2, out, M, FFN, E);
}

// round 5
// speedup vs baseline: 1.0955x; 1.0955x over previous
#include <cuda_runtime.h>
#include <cstdint>

// FeedForwardQuantum — both GEMMs on mma.sync tf32 tensor cores.
//   q = cos(x[:, :NQ] + theta);  h = relu([q,1] @ W1e^T);  out = h @ W2^T + b2
// GEMM2: M=16384, N=1024, K=4096 (BM=64, BN=256, BK=32, 256 thr, warp tile 32x64).
// W1 fragments and W2 tiles are pre-rounded/pre-packed by prep kernels so the
// main loop is: 4 GEMM1 MMAs + 4 STS.128 (A) + 8 cp.async (B) + 64 GEMM2 MMAs.

#define NQ      10
#define BM      64
#define BN      256
#define BK      32
#define THREADS 256
#define E_DIM   1024
#define K_DIM   4096
#define NCHUNK  (K_DIM / BK)     // 128

// ---- dynamic smem layout (bytes) ----
#define SM_A     0                    // 32 row-pairs * 256B = 8192
#define SM_B     8192                 // 2 stages * BN*128B = 65536
#define SM_Q     73728                // 64 rows * 16 floats = 4096
#define SM_TOTAL 77824

__device__ float  g_q[32768 * NQ];
__device__ float4 g_w1f[NCHUNK * 4 * 32];                 // [kci][j][lane], tf32 bits
__device__ float4 g_w2p[(size_t)E_DIM * NCHUNK * 8];      // [n][kci][kk][tp], tf32 bits, 16MB

// ---------------- helpers ----------------
__device__ __forceinline__ uint32_t smem_u32(const void* p) {
    uint32_t a;
    asm("{ .reg .u64 t; cvta.to.shared.u64 t, %1; cvt.u32.u64 %0, t; }" : "=r"(a) : "l"(p));
    return a;
}
__device__ __forceinline__ uint32_t f2tf32(float f) {
    uint32_t r;
    asm("cvt.rna.tf32.f32 %0, %1;" : "=r"(r) : "f"(f));
    return r;
}
__device__ __forceinline__ void cp16(uint32_t dst, const void* src) {
    asm volatile("cp.async.ca.shared.global [%0], [%1], 16;" :: "r"(dst), "l"(src) : "memory");
}

#define MMA_TF32(d, a0, a1, a2, a3, b0, b1)                             \
    asm volatile(                                                       \
        "mma.sync.aligned.m16n8k8.row.col.f32.tf32.tf32.f32 "           \
        "{%0,%1,%2,%3}, {%4,%5,%6,%7}, {%8,%9}, {%0,%1,%2,%3};"         \
        : "+f"((d)[0]), "+f"((d)[1]), "+f"((d)[2]), "+f"((d)[3])        \
        : "r"(a0), "r"(a1), "r"(a2), "r"(a3), "r"(b0), "r"(b1))

// ---------------- prep kernels ----------------
__global__ void qcos_kernel(const float* __restrict__ x,
                            const float* __restrict__ theta, int M, int E) {
    int t = blockIdx.x * blockDim.x + threadIdx.x;
    if (t >= M) return;
    const float* xr = x + (size_t)t * E;
#pragma unroll
    for (int i = 0; i < NQ; i++) g_q[t * NQ + i] = cosf(xr[i] + __ldg(theta + i));
}

// g_w1f[(kci*4+j)*32 + lane] = tf32 of W1e[kci*32+8j+g][{tg, tg+4, 8+tg, 12+tg}]
// W1e[r][f] = f<10 ? W1[r][f] : (f==10 ? b1[r] : 0)
__global__ void prep_w1_kernel(const float* __restrict__ W1, const float* __restrict__ b1) {
    int id = blockIdx.x * blockDim.x + threadIdx.x;      // 16384 total
    if (id >= NCHUNK * 4 * 32) return;
    int kci = id >> 7, j = (id >> 5) & 3, l = id & 31;
    int g = l >> 2, tg = l & 3;
    int row = kci * 32 + 8 * j + g;
    float v[4];
    int f[4] = {tg, tg + 4, 8 + tg, 12 + tg};
#pragma unroll
    for (int i = 0; i < 4; i++)
        v[i] = (f[i] < NQ) ? W1[(size_t)row * NQ + f[i]] : (f[i] == NQ ? b1[row] : 0.0f);
    float4 o;
    o.x = __uint_as_float(f2tf32(v[0]));
    o.y = __uint_as_float(f2tf32(v[1]));
    o.z = __uint_as_float(f2tf32(v[2]));
    o.w = __uint_as_float(f2tf32(v[3]));
    g_w1f[id] = o;
}

// g_w2p[(n*NCHUNK+kci)*8 + kk*2 + tp] = tf32 of W2[n][k+2tp, k+2tp+4, k+2tp+1, k+2tp+5], k = kci*32+kk*8
__global__ void prep_w2_kernel(const float* __restrict__ W2) {
    int id = blockIdx.x * blockDim.x + threadIdx.x;      // 1048576 total
    int n = id >> 10, r = id & 1023;
    int kci = r >> 3, kk = (r >> 1) & 3, tp = r & 1;
    const float* src = W2 + (size_t)n * K_DIM + kci * 32 + kk * 8 + 2 * tp;
    float4 o;
    o.x = __uint_as_float(f2tf32(src[0]));
    o.y = __uint_as_float(f2tf32(src[4]));
    o.z = __uint_as_float(f2tf32(src[1]));
    o.w = __uint_as_float(f2tf32(src[5]));
    g_w2p[id] = o;
}

// ---------------- main kernel ----------------
__global__ void __launch_bounds__(THREADS, 2)
ffn_kernel(const float* __restrict__ b2, float* __restrict__ out) {
    extern __shared__ char smem[];
    char*  As = smem + SM_A;
    char*  Bs = smem + SM_B;
    float* qs = (float*)(smem + SM_Q);
    const uint32_t bs_u32 = smem_u32(Bs);

    const int tid  = threadIdx.x;
    const int warp = tid >> 5;
    const int lane = tid & 31;
    const int g    = lane >> 2;
    const int tg   = lane & 3;
    const int mblk = blockIdx.x * BM;
    const int nblk = blockIdx.y * BN;

    // swizzles (verified minimal-phase):
    //   A: addr = p*256 + ((col*8) ^ aswz(g)),  aswz = ((g&3)<<5)|((g&4)<<2)
    //   B: addr = n*128 + ((kk*32+tg*8) ^ ((n&7)<<4))
    const uint32_t aswz = ((uint32_t)(g & 3) << 5) | ((uint32_t)(g & 4) << 2);

    // ---- stage q slab: qs[row][16] = {q[0..9], 1.0, 0...} ----
    for (int i = tid; i < BM * 16; i += THREADS) {
        int row = i >> 4, c = i & 15;
        qs[i] = (c < NQ) ? g_q[(size_t)(mblk + row) * NQ + c] : (c == NQ ? 1.0f : 0.0f);
    }

    // ---- cp.async B stage 0, chunk 0 ----
    {
        const float4* src = g_w2p + ((size_t)(nblk + tid) * NCHUNK) * 8;
        const uint32_t dst = bs_u32 + tid * 128;
        const uint32_t nsw = ((uint32_t)(tid & 7) << 4);
#pragma unroll
        for (int b = 0; b < 8; b++) {
            uint32_t o = ((uint32_t)((b >> 1) * 32 + (b & 1) * 16)) ^ nsw;
            cp16(dst + o, src + b);
        }
        asm volatile("cp.async.commit_group;" ::: "memory");
    }

    // ---- prefetch W1 frags, chunk 0 ----
    const int jb = (warp >> 2) * 2;          // this warp's GEMM1 j-pair
    float4 wf0 = g_w1f[(0 * 4 + jb) * 32 + lane];
    float4 wf1 = g_w1f[(0 * 4 + jb + 1) * 32 + lane];

    __syncthreads();                         // qs ready

    // ---- loop-invariant q fragments (tf32) ----
    const int mt = warp & 3;                 // GEMM1 m-tile
    uint32_t qf[2][4];
#pragma unroll
    for (int kk = 0; kk < 2; kk++) {
        qf[kk][0] = f2tf32(qs[(mt * 16 + g    ) * 16 + 8 * kk + tg    ]);
        qf[kk][1] = f2tf32(qs[(mt * 16 + g + 8) * 16 + 8 * kk + tg    ]);
        qf[kk][2] = f2tf32(qs[(mt * 16 + g    ) * 16 + 8 * kk + tg + 4]);
        qf[kk][3] = f2tf32(qs[(mt * 16 + g + 8) * 16 + 8 * kk + tg + 4]);
    }

    float acc[2][8][4];
#pragma unroll
    for (int mi = 0; mi < 2; mi++)
#pragma unroll
        for (int ni = 0; ni < 8; ni++)
#pragma unroll
            for (int j = 0; j < 4; j++) acc[mi][ni][j] = 0.f;

    const int pA = mt * 8 + g;               // GEMM1 A-tile row-pair index
    const int wmg = (warp & 1);              // GEMM2 m half
    const int wng = (warp >> 1) * 64;        // GEMM2 n offset

    for (int kci = 0; kci < NCHUNK; kci++) {
        const int s = kci & 1;

        // ======== phase A: GEMM1 -> As; wait B[s] ========
        {
            float ga[2][4] = {{0.f, 0.f, 0.f, 0.f}, {0.f, 0.f, 0.f, 0.f}};
            MMA_TF32(ga[0], qf[0][0], qf[0][1], qf[0][2], qf[0][3],
                     __float_as_uint(wf0.x), __float_as_uint(wf0.y));
            MMA_TF32(ga[0], qf[1][0], qf[1][1], qf[1][2], qf[1][3],
                     __float_as_uint(wf0.z), __float_as_uint(wf0.w));
            MMA_TF32(ga[1], qf[0][0], qf[0][1], qf[0][2], qf[0][3],
                     __float_as_uint(wf1.x), __float_as_uint(wf1.y));
            MMA_TF32(ga[1], qf[1][0], qf[1][1], qf[1][2], qf[1][3],
                     __float_as_uint(wf1.z), __float_as_uint(wf1.w));
#pragma unroll
            for (int jj = 0; jj < 2; jj++) {
                uint4 v;                                  // (d0, d2, d1, d3)
                v.x = f2tf32(fmaxf(ga[jj][0], 0.f));
                v.y = f2tf32(fmaxf(ga[jj][2], 0.f));
                v.z = f2tf32(fmaxf(ga[jj][1], 0.f));
                v.w = f2tf32(fmaxf(ga[jj][3], 0.f));
                const uint32_t col8 = (uint32_t)((8 * (jb + jj) + 2 * tg) * 8);
                *(uint4*)(As + pA * 256 + (col8 ^ aswz)) = v;
            }
        }
        asm volatile("cp.async.wait_group 0;" ::: "memory");
        __syncthreads();

        // ======== phase B: prefetch next, MMA over stage s ========
        if (kci + 1 < NCHUNK) {
            const float4* src = g_w2p + ((size_t)(nblk + tid) * NCHUNK + (kci + 1)) * 8;
            const uint32_t dst = bs_u32 + (s ^ 1) * (BN * 128) + tid * 128;
            const uint32_t nsw = ((uint32_t)(tid & 7) << 4);
#pragma unroll
            for (int b = 0; b < 8; b++) {
                uint32_t o = ((uint32_t)((b >> 1) * 32 + (b & 1) * 16)) ^ nsw;
                cp16(dst + o, src + b);
            }
            asm volatile("cp.async.commit_group;" ::: "memory");
            wf0 = g_w1f[((kci + 1) * 4 + jb) * 32 + lane];
            wf1 = g_w1f[((kci + 1) * 4 + jb + 1) * 32 + lane];
        }

        char* BsS = Bs + s * (BN * 128);
#pragma unroll
        for (int kk = 0; kk < 4; kk++) {
            const int k0 = kk * 8;
            uint2 a01[2], a23[2];
#pragma unroll
            for (int mi = 0; mi < 2; mi++) {
                const int p = (2 * wmg + mi) * 8 + g;
                a01[mi] = *(const uint2*)(As + p * 256 + (((uint32_t)((k0 + tg    ) * 8)) ^ aswz));
                a23[mi] = *(const uint2*)(As + p * 256 + (((uint32_t)((k0 + tg + 4) * 8)) ^ aswz));
            }
#pragma unroll
            for (int ni = 0; ni < 8; ni++) {
                const int n = wng + ni * 8 + g;
                const uint2 bv = *(const uint2*)(Bs + s * (BN * 128) + n * 128 +
                    (((uint32_t)(kk * 32 + tg * 8)) ^ ((uint32_t)(n & 7) << 4)));
                MMA_TF32(acc[0][ni], a01[0].x, a01[0].y, a23[0].x, a23[0].y, bv.x, bv.y);
                MMA_TF32(acc[1][ni], a01[1].x, a01[1].y, a23[1].x, a23[1].y, bv.x, bv.y);
            }
        }
        (void)BsS;
        __syncthreads();
    }

    // ======== epilogue: out = acc + b2 ========
#pragma unroll
    for (int ni = 0; ni < 8; ni++) {
        const int n0 = nblk + wng + ni * 8 + 2 * tg;
        const float2 bv = *(const float2*)(b2 + n0);
#pragma unroll
        for (int mi = 0; mi < 2; mi++) {
            const int m0 = mblk + wmg * 32 + mi * 16 + g;
            float2 o0, o1;
            o0.x = acc[mi][ni][0] + bv.x;  o0.y = acc[mi][ni][1] + bv.y;
            o1.x = acc[mi][ni][2] + bv.x;  o1.y = acc[mi][ni][3] + bv.y;
            *(float2*)(out + (size_t)m0 * E_DIM + n0)       = o0;
            *(float2*)(out + (size_t)(m0 + 8) * E_DIM + n0) = o1;
        }
    }
}

extern "C" void kernel_launch(void* const* d_in, const int* in_sizes, int n_in,
                              void* d_out, int out_size) {
    const float* x     = (const float*)d_in[0];
    const float* theta = (const float*)d_in[1];
    const float* W1    = (const float*)d_in[2];
    const float* b1    = (const float*)d_in[3];
    const float* W2    = (const float*)d_in[4];
    const float* b2    = (const float*)d_in[5];
    float* out = (float*)d_out;

    const int E = in_sizes[5];        // 1024
    const int M = in_sizes[0] / E;    // 16384

    qcos_kernel<<<(M + 255) / 256, 256>>>(x, theta, M, E);
    prep_w1_kernel<<<(NCHUNK * 4 * 32 + 255) / 256, 256>>>(W1, b1);
    prep_w2_kernel<<<(E_DIM * NCHUNK * 8) / 256, 256>>>(W2);

    cudaFuncSetAttribute(ffn_kernel, cudaFuncAttributeMaxDynamicSharedMemorySize, SM_TOTAL);
    dim3 grid(M / BM, E_DIM / BN);    // (256, 4); x fastest -> W2 n-slice hot in L2
    ffn_kernel<<<grid, THREADS, SM_TOTAL>>>(b2, out);
}

// round 6
// speedup vs baseline: 4.0940x; 3.7369x over previous
#include <cuda_runtime.h>
#include <cuda_fp16.h>
#include <cstdint>

// FeedForwardQuantum — fp16 m16n8k16 mma.sync, both GEMMs on tensor cores.
//   q = cos(x[:, :NQ] + theta)            (qcos_kernel -> g_q)
//   h = relu([q,1,0..] @ W1e^T)           (GEMM1, in-loop, MMA)
//   out = h @ W2^T + b2                   (GEMM2, M=16384 N=1024 K=4096)
// W2 pre-converted to fp16 and pre-packed CHUNK-MAJOR with the SMEM swizzle baked
// in, so B staging is 2 coalesced 16-B cp.asyncs per thread from a contiguous block.

#define NQ      10
#define BM      128
#define BN      128
#define BK      32
#define THREADS 256
#define E_DIM   1024
#define K_DIM   4096
#define NCHUNK  (K_DIM / BK)   // 128

// ---- static smem: Bs 2x8KB | As 2x8KB ----
#define SM_B 0
#define SM_A 16384
#define SM_TOTAL 32768

__device__ float g_q[32768 * NQ];            // cos(x+theta), 1.25 MB
__device__ uint2 g_w1h[NCHUNK * 4 * 32];     // W1e fp16 B-fragments per lane, 128 KB
__device__ uint4 g_w2h[NCHUNK * E_DIM * 4];  // W2 fp16 swizzled row images, chunk-major, 8 MB

// ---------------- helpers ----------------
__device__ __forceinline__ uint32_t smem_u32(const void* p) {
    uint32_t a;
    asm("{ .reg .u64 t; cvta.to.shared.u64 t, %1; cvt.u32.u64 %0, t; }" : "=r"(a) : "l"(p));
    return a;
}
__device__ __forceinline__ void cp16(uint32_t dst, const void* src) {
    asm volatile("cp.async.ca.shared.global [%0], [%1], 16;" :: "r"(dst), "l"(src) : "memory");
}
__device__ __forceinline__ uint32_t pack_h2(float lo, float hi) {
    __half2 h = __floats2half2_rn(lo, hi);   // .x = lo, .y = hi
    return *(uint32_t*)&h;
}

#define MMA_F16(d, a0, a1, a2, a3, b0, b1)                              \
    asm volatile(                                                       \
        "mma.sync.aligned.m16n8k16.row.col.f32.f16.f16.f32 "            \
        "{%0,%1,%2,%3}, {%4,%5,%6,%7}, {%8,%9}, {%0,%1,%2,%3};"         \
        : "+f"((d)[0]), "+f"((d)[1]), "+f"((d)[2]), "+f"((d)[3])        \
        : "r"(a0), "r"(a1), "r"(a2), "r"(a3), "r"(b0), "r"(b1))

// Tile row layout (A and B): row r = 64 B (16 half2 "kpairs");
// byte = r*64 + ((kpair*4) ^ ((r&6)<<3)).  Verified conflict-free for all
// STS.32 / LDS.32 patterns used (8 rows x 4 kpairs per warp instruction).
__device__ __forceinline__ uint32_t tile_off(int r, int kpair) {
    return (uint32_t)r * 64u + (((uint32_t)kpair * 4u) ^ (((uint32_t)r & 6u) << 3));
}

// ---------------- prep kernels ----------------
__global__ void qcos_kernel(const float* __restrict__ x,
                            const float* __restrict__ theta, int M, int E) {
    int t = blockIdx.x * blockDim.x + threadIdx.x;
    if (t >= M) return;
    const float* xr = x + (size_t)t * E;
#pragma unroll
    for (int i = 0; i < NQ; i++) g_q[t * NQ + i] = cosf(xr[i] + __ldg(theta + i));
}

// g_w1h[(kci*4+j)*32+lane] = {b0,b1} fp16x2 B-fragments of W1e for h-row group j.
// W1e[r][f] = f<10 ? W1[r][f] : (f==10 ? b1[r] : 0).  b0: f=2tg,2tg+1; b1: f=2tg+8,2tg+9.
__global__ void prep_w1_kernel(const float* __restrict__ W1, const float* __restrict__ b1v) {
    int id = blockIdx.x * blockDim.x + threadIdx.x;
    if (id >= NCHUNK * 4 * 32) return;
    int lane = id & 31, j = (id >> 5) & 3, kci = id >> 7;
    int g = lane >> 2, tg = lane & 3;
    int row = kci * 32 + 8 * j + g;
    float lo0 = W1[(size_t)row * NQ + 2 * tg];
    float hi0 = W1[(size_t)row * NQ + 2 * tg + 1];
    float lo1, hi1;
    if (tg == 0)      { lo1 = W1[(size_t)row * NQ + 8]; hi1 = W1[(size_t)row * NQ + 9]; }
    else if (tg == 1) { lo1 = b1v[row];                 hi1 = 0.f; }
    else              { lo1 = 0.f;                      hi1 = 0.f; }
    uint2 o;
    o.x = pack_h2(lo0, hi0);
    o.y = pack_h2(lo1, hi1);
    g_w1h[id] = o;
}

// g_w2h[(kci*E + n)*4 + c] = 16-B physical chunk c of the swizzled fp16 row image:
// logical chunk lc = c ^ ((n>>1)&3) holds k = kci*32 + 8*lc .. +7 of W2 row n.
__global__ void prep_w2_kernel(const float* __restrict__ W2) {
    int id = blockIdx.x * blockDim.x + threadIdx.x;     // 524288
    if (id >= NCHUNK * E_DIM * 4) return;
    int c = id & 3, n = (id >> 2) & (E_DIM - 1), kci = id >> 12;
    int lc = c ^ ((n >> 1) & 3);
    const float* src = W2 + (size_t)n * K_DIM + kci * 32 + lc * 8;
    uint4 o;
    o.x = pack_h2(src[0], src[1]);
    o.y = pack_h2(src[2], src[3]);
    o.z = pack_h2(src[4], src[5]);
    o.w = pack_h2(src[6], src[7]);
    g_w2h[id] = o;
}

// ---------------- main kernel ----------------
__global__ void __launch_bounds__(THREADS, 2)
ffn_kernel(const float* __restrict__ b2, float* __restrict__ out) {
    __shared__ __align__(128) char smem[SM_TOTAL];

    const int tid  = threadIdx.x;
    const int warp = tid >> 5;
    const int lane = tid & 31;
    const int g    = lane >> 2;
    const int tg   = lane & 3;
    const int mblk = blockIdx.x * BM;
    const int nblk = blockIdx.y * BN;
    const int wm   = (warp & 3) * 32;     // GEMM2 warp m offset
    const int wn   = (warp >> 2) * 64;    // GEMM2 warp n offset

    const uint32_t bs_u32 = smem_u32(smem + SM_B);

    // ---- loop-invariant q fragments (A of GEMM1): rows 16*warp+g (+8), K=16 ----
    uint32_t qf[4];
    {
        const float* q0 = g_q + (size_t)(mblk + 16 * warp + g) * NQ;
        const float* q1 = q0 + 8 * NQ;
        float2 v0 = *(const float2*)(q0 + 2 * tg);       // cols 2tg,2tg+1 (always < 10)
        float2 v1 = *(const float2*)(q1 + 2 * tg);
        qf[0] = pack_h2(v0.x, v0.y);
        qf[1] = pack_h2(v1.x, v1.y);
        if (tg == 0) {                                   // cols 8,9
            float2 w0 = *(const float2*)(q0 + 8);
            float2 w1 = *(const float2*)(q1 + 8);
            qf[2] = pack_h2(w0.x, w0.y);
            qf[3] = pack_h2(w1.x, w1.y);
        } else if (tg == 1) {                            // cols 10,11 -> (1, 0): bias lane
            qf[2] = pack_h2(1.f, 0.f);
            qf[3] = qf[2];
        } else {                                         // cols >= 12 -> 0
            qf[2] = 0u;
            qf[3] = 0u;
        }
    }

    // ---- prologue: stage B chunk 0, W1 frags chunk 0 ----
    {
        const uint4* src = g_w2h + (size_t)nblk * 4;     // chunk 0, rows nblk..nblk+127
        cp16(bs_u32 + 16u * tid,         src + tid);
        cp16(bs_u32 + 16u * (tid + 256), src + tid + 256);
        asm volatile("cp.async.commit_group;" ::: "memory");
    }
    uint2 wf[4], wfn[4];
#pragma unroll
    for (int j = 0; j < 4; j++) wf[j] = g_w1h[j * 32 + lane];

    float acc[2][8][4];
#pragma unroll
    for (int mi = 0; mi < 2; mi++)
#pragma unroll
        for (int ni = 0; ni < 8; ni++)
#pragma unroll
            for (int v = 0; v < 4; v++) acc[mi][ni][v] = 0.f;

    for (int kci = 0; kci < NCHUNK; kci++) {
        const int s = kci & 1;
        char* As = smem + SM_A + s * 8192;
        char* Bs = smem + SM_B + s * 8192;

        // ======== phase A: GEMM1 -> As[s] ========
#pragma unroll
        for (int j = 0; j < 4; j++) {
            float ga[4] = {0.f, 0.f, 0.f, 0.f};
            MMA_F16(ga, qf[0], qf[1], qf[2], qf[3], wf[j].x, wf[j].y);
            const int m0 = 16 * warp + g;
            const int kp = 4 * j + tg;
            *(uint32_t*)(As + tile_off(m0,     kp)) = pack_h2(fmaxf(ga[0], 0.f), fmaxf(ga[1], 0.f));
            *(uint32_t*)(As + tile_off(m0 + 8, kp)) = pack_h2(fmaxf(ga[2], 0.f), fmaxf(ga[3], 0.f));
        }
        if (kci + 1 < NCHUNK) {
#pragma unroll
            for (int j = 0; j < 4; j++) wfn[j] = g_w1h[((kci + 1) * 4 + j) * 32 + lane];
        }

        asm volatile("cp.async.wait_group 0;" ::: "memory");
        __syncthreads();   // single barrier per chunk (double-buffered A and B)

        // ======== phase B: stage next B; GEMM2 over stage s ========
        if (kci + 1 < NCHUNK) {
            const uint4* src = g_w2h + ((size_t)(kci + 1) * E_DIM + nblk) * 4;
            const uint32_t dst = bs_u32 + (uint32_t)(s ^ 1) * 8192u;
            cp16(dst + 16u * tid,         src + tid);
            cp16(dst + 16u * (tid + 256), src + tid + 256);
            asm volatile("cp.async.commit_group;" ::: "memory");
        }

#pragma unroll
        for (int kk2 = 0; kk2 < 2; kk2++) {
            const int kp = 8 * kk2 + tg;
            uint32_t a[2][4];
#pragma unroll
            for (int mi = 0; mi < 2; mi++) {
                const int r0 = wm + 16 * mi + g;
                a[mi][0] = *(const uint32_t*)(As + tile_off(r0,     kp));
                a[mi][1] = *(const uint32_t*)(As + tile_off(r0 + 8, kp));
                a[mi][2] = *(const uint32_t*)(As + tile_off(r0,     kp + 4));
                a[mi][3] = *(const uint32_t*)(As + tile_off(r0 + 8, kp + 4));
            }
#pragma unroll
            for (int ni = 0; ni < 8; ni++) {
                const int n = wn + 8 * ni + g;
                const uint32_t b0 = *(const uint32_t*)(Bs + tile_off(n, kp));
                const uint32_t b1 = *(const uint32_t*)(Bs + tile_off(n, kp + 4));
                MMA_F16(acc[0][ni], a[0][0], a[0][1], a[0][2], a[0][3], b0, b1);
                MMA_F16(acc[1][ni], a[1][0], a[1][1], a[1][2], a[1][3], b0, b1);
            }
        }

        if (kci + 1 < NCHUNK) {
#pragma unroll
            for (int j = 0; j < 4; j++) wf[j] = wfn[j];
        }
    }

    // ======== epilogue: out = acc + b2 ========
#pragma unroll
    for (int ni = 0; ni < 8; ni++) {
        const int n0 = nblk + wn + 8 * ni + 2 * tg;
        const float2 bv = *(const float2*)(b2 + n0);
#pragma unroll
        for (int mi = 0; mi < 2; mi++) {
            const int m0 = mblk + wm + 16 * mi + g;
            float2 o0, o1;
            o0.x = acc[mi][ni][0] + bv.x;  o0.y = acc[mi][ni][1] + bv.y;
            o1.x = acc[mi][ni][2] + bv.x;  o1.y = acc[mi][ni][3] + bv.y;
            *(float2*)(out + (size_t)m0 * E_DIM + n0)       = o0;
            *(float2*)(out + (size_t)(m0 + 8) * E_DIM + n0) = o1;
        }
    }
}

extern "C" void kernel_launch(void* const* d_in, const int* in_sizes, int n_in,
                              void* d_out, int out_size) {
    const float* x     = (const float*)d_in[0];
    const float* theta = (const float*)d_in[1];
    const float* W1    = (const float*)d_in[2];
    const float* b1v   = (const float*)d_in[3];
    const float* W2    = (const float*)d_in[4];
    const float* b2    = (const float*)d_in[5];
    float* out = (float*)d_out;

    const int E = in_sizes[5];        // 1024
    const int M = in_sizes[0] / E;    // 16384

    qcos_kernel<<<(M + 255) / 256, 256>>>(x, theta, M, E);
    prep_w1_kernel<<<(NCHUNK * 4 * 32 + 255) / 256, 256>>>(W1, b1v);
    prep_w2_kernel<<<(NCHUNK * E_DIM * 4) / 256, 256>>>(W2);

    dim3 grid(M / BM, E_DIM / BN);    // (128, 8); x fastest -> chunk tiles shared in L2
    ffn_kernel<<<grid, THREADS>>>(b2, out);
}